// round 2
// baseline (speedup 1.0000x reference)
#include <cuda_runtime.h>
#include <cuda_bf16.h>

// ShortConv: causal depthwise Conv1d (K=4) + SiLU.
// x: (B=4, L=4096, D=2048) fp32, D contiguous. w: (D, 1, 4) fp32.
// y[b,l,d] = silu( sum_{k=0..3} w[d,0,k] * x[b, l-3+k, d] ), x out of range -> 0.
//
// Strategy: HBM-bound (AI ~1.8 FLOP/B). Vectorize float4 across D for coalescing;
// each thread owns one float4 D-column and slides a 3-row register window along a
// 64-long L chunk, so x is read from DRAM exactly once and y written exactly once
// (256 MiB total traffic). #pragma unroll 4 -> 4 independent loads in flight.

#define DIM      2048
#define D4       (DIM / 4)      // 512 float4 per row
#define SEQLEN   4096
#define BATCH    4
#define THREADS  256            // float4 lanes per block
#define DGROUPS  (D4 / THREADS) // 2
#define LCHUNK   64

__device__ __forceinline__ float silu1(float v) {
    return v * (1.0f / (1.0f + __expf(-v)));
}

__global__ __launch_bounds__(THREADS)
void shortconv_silu_kernel(const float4* __restrict__ x,
                           const float4* __restrict__ w4,
                           float4* __restrict__ y) {
    const int d4 = blockIdx.y * THREADS + threadIdx.x;  // 0..511 (which float4 of D)
    const int b  = blockIdx.z;
    const int l0 = blockIdx.x * LCHUNK;

    // Per-channel taps: w floats are [d*4 + k]; channels d0..d0+3 of this lane
    // are 16 contiguous floats = 4 contiguous float4s starting at index d4*4.
    const float4 wa = w4[d4 * 4 + 0];  // channel d0   taps k0..k3
    const float4 wb = w4[d4 * 4 + 1];  // channel d0+1
    const float4 wc = w4[d4 * 4 + 2];  // channel d0+2
    const float4 wd = w4[d4 * 4 + 3];  // channel d0+3

    const float4* xb = x + (size_t)b * SEQLEN * D4 + d4;
    float4*       yb = y + (size_t)b * SEQLEN * D4 + d4;

    const float4 zero = make_float4(0.f, 0.f, 0.f, 0.f);
    // Preload the 3 rows preceding this chunk (zeros for l < 0: causal pad).
    float4 xm3 = (l0 >= 3) ? xb[(size_t)(l0 - 3) * D4] : zero;
    float4 xm2 = (l0 >= 2) ? xb[(size_t)(l0 - 2) * D4] : zero;
    float4 xm1 = (l0 >= 1) ? xb[(size_t)(l0 - 1) * D4] : zero;

    #pragma unroll 4
    for (int i = 0; i < LCHUNK; ++i) {
        const size_t row = (size_t)(l0 + i) * D4;
        const float4 xc = xb[row];

        float4 r;
        r.x = fmaf(wa.x, xm3.x, fmaf(wa.y, xm2.x, fmaf(wa.z, xm1.x, wa.w * xc.x)));
        r.y = fmaf(wb.x, xm3.y, fmaf(wb.y, xm2.y, fmaf(wb.z, xm1.y, wb.w * xc.y)));
        r.z = fmaf(wc.x, xm3.z, fmaf(wc.y, xm2.z, fmaf(wc.z, xm1.z, wc.w * xc.z)));
        r.w = fmaf(wd.x, xm3.w, fmaf(wd.y, xm2.w, fmaf(wd.z, xm1.w, wd.w * xc.w)));

        r.x = silu1(r.x);
        r.y = silu1(r.y);
        r.z = silu1(r.z);
        r.w = silu1(r.w);

        yb[row] = r;

        xm3 = xm2; xm2 = xm1; xm1 = xc;
    }
}

extern "C" void kernel_launch(void* const* d_in, const int* in_sizes, int n_in,
                              void* d_out, int out_size) {
    const float4* x  = (const float4*)d_in[0];
    const float4* w4 = (const float4*)d_in[1];
    float4*       y  = (float4*)d_out;

    dim3 grid(SEQLEN / LCHUNK, DGROUPS, BATCH);  // (64, 2, 4) = 512 CTAs
    shortconv_silu_kernel<<<grid, THREADS>>>(x, w4, y);
}

// round 3
// speedup vs baseline: 1.0942x; 1.0942x over previous
#include <cuda_runtime.h>
#include <cuda_bf16.h>

// ShortConv: causal depthwise Conv1d (K=4) + SiLU.
// x: (B=4, L=4096, D=2048) fp32, D contiguous. w: (D, 1, 4) fp32.
// y[b,l,d] = silu( sum_{k=0..3} w[d,0,k] * x[b, l-3+k, d] ), OOB x -> 0.
//
// R2 changes vs R1 (71.7us, occ 41.9%, DRAM 41.9% -> latency/occupancy bound):
//  - __launch_bounds__(256,5): cap regs ~51 -> 40 warps/SM (62.5% occ).
//  - LCHUNK 32 -> 1024 CTAs (wave smoothing; halo read overhead 9%).
//  - Pointer-increment addressing: one 64-bit base, immediate offsets in the
//    unrolled loop (kills per-iter IMAD.WIDE chains seen as alu=14.7%).
//  - SiLU via tanh.approx (1 MUFU) instead of EX2+RCP (2 MUFU + extra ALU).
//  - __ldcs/__stcs streaming hints (data is read/written exactly once).

#define DIM      2048
#define D4       (DIM / 4)      // 512 float4 per row
#define SEQLEN   4096
#define BATCH    4
#define THREADS  256
#define DGROUPS  (D4 / THREADS) // 2
#define LCHUNK   32

__device__ __forceinline__ float silu1(float v) {
    // silu(v) = v * sigmoid(v) = 0.5*v*(1 + tanh(v/2)); tanh.approx = 1 MUFU.
    float t, h = 0.5f * v;
    asm("tanh.approx.f32 %0, %1;" : "=f"(t) : "f"(h));
    return fmaf(h, t, h);
}

__global__ __launch_bounds__(THREADS, 5)
void shortconv_silu_kernel(const float4* __restrict__ x,
                           const float4* __restrict__ w4,
                           float4* __restrict__ y) {
    const int d4 = blockIdx.y * THREADS + threadIdx.x;  // which float4 of D
    const int b  = blockIdx.z;
    const int l0 = blockIdx.x * LCHUNK;

    // Channel taps: w floats are [d*4+k]; this lane's 4 channels = 4 contiguous float4.
    const float4 wa = w4[d4 * 4 + 0];
    const float4 wb = w4[d4 * 4 + 1];
    const float4 wc = w4[d4 * 4 + 2];
    const float4 wd = w4[d4 * 4 + 3];

    const float4* xp = x + ((size_t)b * SEQLEN + l0) * D4 + d4;
    float4*       yp = y + ((size_t)b * SEQLEN + l0) * D4 + d4;

    const float4 zero = make_float4(0.f, 0.f, 0.f, 0.f);
    // Preload the 3 preceding rows (zeros for l<0: causal pad). Uniform branch per CTA.
    float4 xm3, xm2, xm1;
    if (l0 >= 3) {
        xm3 = __ldcs(xp - 3 * D4);
        xm2 = __ldcs(xp - 2 * D4);
        xm1 = __ldcs(xp - 1 * D4);
    } else {
        xm3 = zero; xm2 = zero; xm1 = zero;  // only blockIdx.x==0 (l0==0)
    }

    #pragma unroll 4
    for (int i = 0; i < LCHUNK; ++i) {
        const float4 xc = __ldcs(xp + i * D4);

        float4 r;
        r.x = fmaf(wa.x, xm3.x, fmaf(wa.y, xm2.x, fmaf(wa.z, xm1.x, wa.w * xc.x)));
        r.y = fmaf(wb.x, xm3.y, fmaf(wb.y, xm2.y, fmaf(wb.z, xm1.y, wb.w * xc.y)));
        r.z = fmaf(wc.x, xm3.z, fmaf(wc.y, xm2.z, fmaf(wc.z, xm1.z, wc.w * xc.z)));
        r.w = fmaf(wd.x, xm3.w, fmaf(wd.y, xm2.w, fmaf(wd.z, xm1.w, wd.w * xc.w)));

        r.x = silu1(r.x);
        r.y = silu1(r.y);
        r.z = silu1(r.z);
        r.w = silu1(r.w);

        __stcs(yp + i * D4, r);

        xm3 = xm2; xm2 = xm1; xm1 = xc;
    }
}

extern "C" void kernel_launch(void* const* d_in, const int* in_sizes, int n_in,
                              void* d_out, int out_size) {
    const float4* x  = (const float4*)d_in[0];
    const float4* w4 = (const float4*)d_in[1];
    float4*       y  = (float4*)d_out;

    dim3 grid(SEQLEN / LCHUNK, DGROUPS, BATCH);  // (128, 2, 4) = 1024 CTAs
    shortconv_silu_kernel<<<grid, THREADS>>>(x, w4, y);
}

// round 4
// speedup vs baseline: 1.1183x; 1.0220x over previous
#include <cuda_runtime.h>
#include <cuda_bf16.h>

// ShortConv: causal depthwise Conv1d (K=4) + SiLU.
// x: (B=4, L=4096, D=2048) fp32, D contiguous. w: (D, 1, 4) fp32.
// y[b,l,d] = silu( sum_{k=0..3} w[d,0,k] * x[b, l-3+k, d] ), OOB x -> 0.
//
// R3 vs R2 (65.5us; occ 45.6% < 62.5% cap, DRAM 48.8%, nothing saturated):
//  Diagnosis: 1024 CTAs at occ-limit 5/SM = 1.38 waves; wave-2 runs 38% full.
//  Fix: single full wave (740 CTAs = 148 SMs x 5) pulling 32-row work units
//  from a global atomic ticket (1024 units) -> balance error <= 1 unit.
//  Ticket reset by a tiny kernel launched first (graph-capturable, no allocs).

#define DIM      2048
#define D4       (DIM / 4)      // 512 float4 per row
#define SEQLEN   4096
#define BATCH    4
#define THREADS  256
#define LCHUNK   32
#define NCHUNKS  (SEQLEN / LCHUNK)              // 128
#define DGROUPS  (D4 / THREADS)                 // 2
#define NUNITS   (BATCH * DGROUPS * NCHUNKS)    // 1024
#define NCTAS    740                            // 148 SMs x occ 5

__device__ unsigned int g_ticket;

__global__ void reset_ticket() { g_ticket = 0u; }

__device__ __forceinline__ float silu1(float v) {
    // silu(v) = 0.5*v*(1 + tanh(v/2)); tanh.approx = 1 MUFU.
    float t, h = 0.5f * v;
    asm("tanh.approx.f32 %0, %1;" : "=f"(t) : "f"(h));
    return fmaf(h, t, h);
}

__global__ __launch_bounds__(THREADS, 5)
void shortconv_silu_kernel(const float4* __restrict__ x,
                           const float4* __restrict__ w4,
                           float4* __restrict__ y) {
    __shared__ unsigned int s_unit;

    for (;;) {
        if (threadIdx.x == 0)
            s_unit = atomicAdd(&g_ticket, 1u);
        __syncthreads();
        const unsigned int u = s_unit;
        __syncthreads();   // protect s_unit before next overwrite
        if (u >= NUNITS) return;

        // Decode unit: u = ((b * DGROUPS) + dg) * NCHUNKS + chunk
        const int chunk = u & (NCHUNKS - 1);
        const int bd    = u >> 7;            // b*DGROUPS + dg
        const int dg    = bd & (DGROUPS - 1);
        const int b     = bd >> 1;

        const int d4 = dg * THREADS + threadIdx.x;
        const int l0 = chunk * LCHUNK;

        // Channel taps: w floats are [d*4+k]; this lane's 4 channels = 4 contiguous float4.
        const float4 wa = w4[d4 * 4 + 0];
        const float4 wb = w4[d4 * 4 + 1];
        const float4 wc = w4[d4 * 4 + 2];
        const float4 wd = w4[d4 * 4 + 3];

        const float4* xp = x + ((size_t)b * SEQLEN + l0) * D4 + d4;
        float4*       yp = y + ((size_t)b * SEQLEN + l0) * D4 + d4;

        const float4 zero = make_float4(0.f, 0.f, 0.f, 0.f);
        float4 xm3, xm2, xm1;
        if (l0 >= 3) {   // uniform per unit
            xm3 = __ldcs(xp - 3 * D4);
            xm2 = __ldcs(xp - 2 * D4);
            xm1 = __ldcs(xp - 1 * D4);
        } else {         // only chunk==0: causal zero pad
            xm3 = zero; xm2 = zero; xm1 = zero;
        }

        #pragma unroll 4
        for (int i = 0; i < LCHUNK; ++i) {
            const float4 xc = __ldcs(xp + i * D4);

            float4 r;
            r.x = fmaf(wa.x, xm3.x, fmaf(wa.y, xm2.x, fmaf(wa.z, xm1.x, wa.w * xc.x)));
            r.y = fmaf(wb.x, xm3.y, fmaf(wb.y, xm2.y, fmaf(wb.z, xm1.y, wb.w * xc.y)));
            r.z = fmaf(wc.x, xm3.z, fmaf(wc.y, xm2.z, fmaf(wc.z, xm1.z, wc.w * xc.z)));
            r.w = fmaf(wd.x, xm3.w, fmaf(wd.y, xm2.w, fmaf(wd.z, xm1.w, wd.w * xc.w)));

            r.x = silu1(r.x);
            r.y = silu1(r.y);
            r.z = silu1(r.z);
            r.w = silu1(r.w);

            __stcs(yp + i * D4, r);

            xm3 = xm2; xm2 = xm1; xm1 = xc;
        }
    }
}

extern "C" void kernel_launch(void* const* d_in, const int* in_sizes, int n_in,
                              void* d_out, int out_size) {
    const float4* x  = (const float4*)d_in[0];
    const float4* w4 = (const float4*)d_in[1];
    float4*       y  = (float4*)d_out;

    reset_ticket<<<1, 1>>>();
    shortconv_silu_kernel<<<NCTAS, THREADS>>>(x, w4, y);
}

// round 5
// speedup vs baseline: 1.3067x; 1.1685x over previous
#include <cuda_runtime.h>
#include <cuda_bf16.h>

// ShortConv: causal depthwise Conv1d (K=4) + SiLU.
// x: (B=4, L=4096, D=2048) fp32, D contiguous. w: (D, 1, 4) fp32.
// y[b,l,d] = silu( sum_{k=0..3} w[d,0,k] * x[b, l-3+k, d] ), OOB x -> 0.
//
// R4 vs R3 (64.1us; occ 46.5%: 1024 units / 740 CTAs -> 2-vs-1 unit imbalance):
//  Static row-granular balance. 8 (b,dg) columns x 4096 rows = 32768 row-tasks,
//  CTA c owns rows [c*32768/740, (c+1)*32768/740): 44-45 rows each (<=2.3%
//  imbalance). Segment loop restarts the sliding window at column boundaries
//  (at most 1 crossing per CTA; halo ~3 rows/segment ~3.4% extra reads).

#define DIM        2048
#define D4         (DIM / 4)       // 512 float4 per row
#define SEQLEN     4096
#define BATCH      4
#define THREADS    256
#define DGROUPS    (D4 / THREADS)  // 2
#define NCOLS      (BATCH * DGROUPS)          // 8
#define TOTAL_ROWS (NCOLS * SEQLEN)           // 32768
#define NCTAS      740                        // 148 SMs x occ 5

__device__ __forceinline__ float silu1(float v) {
    // silu(v) = 0.5*v*(1 + tanh(v/2)); tanh.approx = 1 MUFU.
    float t, h = 0.5f * v;
    asm("tanh.approx.f32 %0, %1;" : "=f"(t) : "f"(h));
    return fmaf(h, t, h);
}

__global__ __launch_bounds__(THREADS, 5)
void shortconv_silu_kernel(const float4* __restrict__ x,
                           const float4* __restrict__ w4,
                           float4* __restrict__ y) {
    const unsigned int cta = blockIdx.x;
    unsigned int r0 = (unsigned int)(((unsigned long long)cta       * TOTAL_ROWS) / NCTAS);
    const unsigned int r1 = (unsigned int)(((unsigned long long)(cta + 1) * TOTAL_ROWS) / NCTAS);

    const float4 zero = make_float4(0.f, 0.f, 0.f, 0.f);

    while (r0 < r1) {
        const unsigned int c = r0 >> 12;            // column: b*DGROUPS + dg
        const unsigned int l = r0 & (SEQLEN - 1);   // row within column
        const unsigned int seg_end = min(r1, (c + 1) << 12);
        const int n = (int)(seg_end - r0);

        const int dg = c & (DGROUPS - 1);
        const int b  = c >> 1;
        const int d4 = dg * THREADS + threadIdx.x;

        // Channel taps: w floats are [d*4+k]; this lane's 4 channels = 4 contiguous float4.
        const float4 wa = w4[d4 * 4 + 0];
        const float4 wb = w4[d4 * 4 + 1];
        const float4 wc = w4[d4 * 4 + 2];
        const float4 wd = w4[d4 * 4 + 3];

        const float4* xp = x + ((size_t)b * SEQLEN + l) * D4 + d4;
        float4*       yp = y + ((size_t)b * SEQLEN + l) * D4 + d4;

        // Preload the 3 preceding rows (zeros where l-k < 0: causal pad).
        float4 xm3 = (l >= 3) ? __ldcs(xp - 3 * D4) : zero;
        float4 xm2 = (l >= 2) ? __ldcs(xp - 2 * D4) : zero;
        float4 xm1 = (l >= 1) ? __ldcs(xp - 1 * D4) : zero;

        #pragma unroll 4
        for (int i = 0; i < n; ++i) {
            const float4 xc = __ldcs(xp + i * D4);

            float4 r;
            r.x = fmaf(wa.x, xm3.x, fmaf(wa.y, xm2.x, fmaf(wa.z, xm1.x, wa.w * xc.x)));
            r.y = fmaf(wb.x, xm3.y, fmaf(wb.y, xm2.y, fmaf(wb.z, xm1.y, wb.w * xc.y)));
            r.z = fmaf(wc.x, xm3.z, fmaf(wc.y, xm2.z, fmaf(wc.z, xm1.z, wc.w * xc.z)));
            r.w = fmaf(wd.x, xm3.w, fmaf(wd.y, xm2.w, fmaf(wd.z, xm1.w, wd.w * xc.w)));

            r.x = silu1(r.x);
            r.y = silu1(r.y);
            r.z = silu1(r.z);
            r.w = silu1(r.w);

            __stcs(yp + i * D4, r);

            xm3 = xm2; xm2 = xm1; xm1 = xc;
        }

        r0 = seg_end;
    }
}

extern "C" void kernel_launch(void* const* d_in, const int* in_sizes, int n_in,
                              void* d_out, int out_size) {
    const float4* x  = (const float4*)d_in[0];
    const float4* w4 = (const float4*)d_in[1];
    float4*       y  = (float4*)d_out;

    shortconv_silu_kernel<<<NCTAS, THREADS>>>(x, w4, y);
}

// round 7
// speedup vs baseline: 1.3998x; 1.0712x over previous
#include <cuda_runtime.h>
#include <cuda_bf16.h>
#include <cstdint>

// ShortConv: causal depthwise Conv1d (K=4) + SiLU.
// x: (B=4, L=4096, D=2048) fp32, D contiguous. w: (D, 1, 4) fp32.
// y[b,l,d] = silu( sum_{k=0..3} w[d,0,k] * x[b, l-3+k, d] ), OOB x -> 0.
//
// R6 = R5 resubmit (R5 bench died at container level before running; infra,
// same failure mode as R1's empty-stub round).
//
// R5 vs R4 (54.9us; occ 58.6% ~= cap, DRAM 56%, issue 21% -> exposed-latency
// bound; LDG MLP capped ~3-4 by regs=48):
//  cp.async.cg 16B/thread into an 8-stage smem ring (thread-private slots, no
//  syncthreads). Pipeline depth 7 in flight per thread, independent of reg
//  pressure -> ~2x outstanding bytes/SM. L1 bypassed (.cg) for streaming x.

#define DIM        2048
#define D4         (DIM / 4)       // 512 float4 per row
#define SEQLEN     4096
#define BATCH      4
#define THREADS    256
#define DGROUPS    (D4 / THREADS)  // 2
#define NCOLS      (BATCH * DGROUPS)          // 8
#define TOTAL_ROWS (NCOLS * SEQLEN)           // 32768
#define NCTAS      740                        // 148 SMs x occ 5
#define STAGES     8
#define STAGE_BYTES (THREADS * 16)            // 4KB per stage

__device__ __forceinline__ void cp_async16(uint32_t dst_smem, const void* src) {
    asm volatile("cp.async.cg.shared.global [%0], [%1], 16;\n"
                 :: "r"(dst_smem), "l"(src));
}
__device__ __forceinline__ void cp_commit() {
    asm volatile("cp.async.commit_group;\n");
}
__device__ __forceinline__ void cp_wait_allbutN() {  // wait until <= STAGES-2 pending
    asm volatile("cp.async.wait_group %0;\n" :: "n"(STAGES - 2));
}

__device__ __forceinline__ float silu1(float v) {
    // silu(v) = 0.5*v*(1 + tanh(v/2)); tanh.approx = 1 MUFU.
    float t, h = 0.5f * v;
    asm("tanh.approx.f32 %0, %1;" : "=f"(t) : "f"(h));
    return fmaf(h, t, h);
}

__global__ __launch_bounds__(THREADS, 5)
void shortconv_silu_kernel(const float4* __restrict__ x,
                           const float4* __restrict__ w4,
                           float4* __restrict__ y) {
    __shared__ float4 ring[STAGES][THREADS];

    const uint32_t ring_base =
        (uint32_t)__cvta_generic_to_shared(&ring[0][threadIdx.x]);

    const unsigned int cta = blockIdx.x;
    unsigned int r0 = (unsigned int)(((unsigned long long)cta       * TOTAL_ROWS) / NCTAS);
    const unsigned int r1 = (unsigned int)(((unsigned long long)(cta + 1) * TOTAL_ROWS) / NCTAS);

    const float4 zero = make_float4(0.f, 0.f, 0.f, 0.f);

    while (r0 < r1) {
        const unsigned int c = r0 >> 12;            // column: b*DGROUPS + dg
        const unsigned int l = r0 & (SEQLEN - 1);   // row within column
        const unsigned int seg_end = min(r1, (c + 1) << 12);
        const int n = (int)(seg_end - r0);

        const int dg = c & (DGROUPS - 1);
        const int b  = c >> 1;
        const int d4 = dg * THREADS + threadIdx.x;

        // Channel taps: w floats are [d*4+k]; this lane's 4 channels = 4 contiguous float4.
        const float4 wa = w4[d4 * 4 + 0];
        const float4 wb = w4[d4 * 4 + 1];
        const float4 wc = w4[d4 * 4 + 2];
        const float4 wd = w4[d4 * 4 + 3];

        const float4* xp = x + ((size_t)b * SEQLEN + l) * D4 + d4;
        float4*       yp = y + ((size_t)b * SEQLEN + l) * D4 + d4;

        // Causal window preload (plain loads; overlap with pipeline prologue).
        float4 xm3 = (l >= 3) ? __ldcs(xp - 3 * D4) : zero;
        float4 xm2 = (l >= 2) ? __ldcs(xp - 2 * D4) : zero;
        float4 xm1 = (l >= 1) ? __ldcs(xp - 1 * D4) : zero;

        // Pipeline prologue: issue rows 0..STAGES-2 (guarded), one group each.
        #pragma unroll
        for (int s = 0; s < STAGES - 1; ++s) {
            if (s < n) cp_async16(ring_base + s * STAGE_BYTES, xp + s * D4);
            cp_commit();
        }

        #pragma unroll 2
        for (int i = 0; i < n; ++i) {
            cp_wait_allbutN();                     // row i's group complete
            const float4 xc = ring[i & (STAGES - 1)][threadIdx.x];

            // Refill: row i+STAGES-1 into the stage freed last iteration.
            const int il = i + (STAGES - 1);
            if (il < n)
                cp_async16(ring_base + (il & (STAGES - 1)) * STAGE_BYTES, xp + il * D4);
            cp_commit();

            float4 r;
            r.x = fmaf(wa.x, xm3.x, fmaf(wa.y, xm2.x, fmaf(wa.z, xm1.x, wa.w * xc.x)));
            r.y = fmaf(wb.x, xm3.y, fmaf(wb.y, xm2.y, fmaf(wb.z, xm1.y, wb.w * xc.y)));
            r.z = fmaf(wc.x, xm3.z, fmaf(wc.y, xm2.z, fmaf(wc.z, xm1.z, wc.w * xc.z)));
            r.w = fmaf(wd.x, xm3.w, fmaf(wd.y, xm2.w, fmaf(wd.z, xm1.w, wd.w * xc.w)));

            r.x = silu1(r.x);
            r.y = silu1(r.y);
            r.z = silu1(r.z);
            r.w = silu1(r.w);

            __stcs(yp + i * D4, r);

            xm3 = xm2; xm2 = xm1; xm1 = xc;
        }

        r0 = seg_end;
    }
}

extern "C" void kernel_launch(void* const* d_in, const int* in_sizes, int n_in,
                              void* d_out, int out_size) {
    const float4* x  = (const float4*)d_in[0];
    const float4* w4 = (const float4*)d_in[1];
    float4*       y  = (float4*)d_out;

    shortconv_silu_kernel<<<NCTAS, THREADS>>>(x, w4, y);
}